// round 9
// baseline (speedup 1.0000x reference)
#include <cuda_runtime.h>
#include <cstdint>

// Model_NPZD_68401649156380 — R9: autonomous per-warp pipelines with
// row-coalesced cp.async. Warp = 32 consecutive ODEs. Per chunk (8 steps),
// each ODE row needs the contiguous 24-float span gf[row, 24c .. 24c+23]
// (used cols are 24c+3i). One cp.async warp-instruction per (row, array):
// lanes 0..23 fetch contiguous 4B -> 1-2 L1 wavefronts. 64 instrs/chunk,
// 2-slot smem ring per warp, no __syncthreads anywhere.

#define NB      2048
#define NWK     52
#define NHRS    8760
#define DT      0.125f
#define NT      128
#define WPB     (NT / 32)              // 4 warps per block
#define NCH     7
#define ROWF    50                     // floats per ODE row: 24 f | pad | 24 m | pad
#define SLOTF   (32 * ROWF)            // 1600 floats per slot
#define WSLAB   (2 * SLOTF)            // 3200 floats per warp (2 slots)
#define SMEM_BYTES (WPB * WSLAB * 4)   // 51200
#define GRID    ((NB * NWK) / (32 * WPB))   // 832

__device__ __forceinline__ void issue_chunk(
    const float* __restrict__ gf, const float* __restrict__ gm,
    int off0, int rwrap, int c, uint32_t slot_sh, int lane)
{
    if (lane < 24) {
        const int col = 24 * c + lane;
        #pragma unroll
        for (int r = 0; r < 32; ++r) {
            int off = off0 + 168 * r + ((r >= rwrap) ? 24 : 0) + col;
            uint32_t d = slot_sh + (uint32_t)((r * ROWF + lane) * 4);
            asm volatile("cp.async.ca.shared.global [%0], [%1], 4;\n"
                         :: "r"(d), "l"(gf + off) : "memory");
            asm volatile("cp.async.ca.shared.global [%0], [%1], 4;\n"
                         :: "r"(d + 25 * 4), "l"(gm + off) : "memory");
        }
    }
    asm volatile("cp.async.commit_group;\n" ::: "memory");
}

__global__ __launch_bounds__(NT, 4) void npzd_kernel(
    const float* __restrict__ X_in,     // (B, 52, 5, 1)
    const float* __restrict__ gf,       // (B, 8760)
    const float* __restrict__ gm,       // (B, 8760)
    const float* __restrict__ pv,       // (B, 10)
    float* __restrict__ out)            // (B, 52, 4, 8)
{
    extern __shared__ float slabs[];    // [WPB][2][SLOTF]
    const int lane = threadIdx.x & 31;
    const int wid  = threadIdx.x >> 5;
    const int Wg   = blockIdx.x * WPB + wid;
    const int t0   = Wg * 32;           // first ODE of this warp
    const int t    = t0 + lane;

    // Uniform warp bases; at most one w-wrap inside 32 consecutive ODEs.
    const int b0 = t0 / NWK;
    const int w0 = t0 - b0 * NWK;
    const int off0  = b0 * NHRS + 168 * w0;
    const int rwrap = NWK - w0;         // first r with wrapped w (may be >=32)

    float* slab = slabs + wid * WSLAB;
    uint32_t slab_sh = (uint32_t)__cvta_generic_to_shared(slab);

    // Prime: chunks 0 and 1 in flight.
    issue_chunk(gf, gm, off0, rwrap, 0, slab_sh, lane);
    issue_chunk(gf, gm, off0, rwrap, 1, slab_sh + SLOTF * 4, lane);

    // Per-lane ODE identity (cheap, no division).
    int w = w0 + lane, badd = 0;
    if (w >= NWK) { w -= NWK; badd = 1; }
    const int b = b0 + badd;

    // Params + initial state (overlaps first gathers).
    const float* p = pv + b * 10;
    const float chiC   = p[0];
    const float rho2   = p[1] * 2.0f;
    const float gam01  = p[2] * 0.1f;
    const float lam005 = p[3] * 0.05f;
    const float eps01  = p[4] * 0.1f;
    const float alp03  = p[5] * 0.3f;
    const float bet06  = p[6] * 0.6f;
    const float eta015 = p[7] * 0.15f;
    const float phi04  = p[8] * 0.4f;
    const float zet01  = p[9] * 0.1f;
    const float rem    = 1.0f - alp03 - bet06;

    const float* xi = X_in + (size_t)t * 5;
    float N = xi[1], P = xi[2], Z = xi[3], D = xi[4];

    float o[4][8];
    o[0][0] = N; o[1][0] = P; o[2][0] = Z; o[3][0] = D;

    #pragma unroll 1
    for (int c = 0; c < NCH; ++c) {
        // Chunk c landed: normally <=1 younger group pending; final chunk
        // has nothing behind it, so drain fully.
        if (c + 1 == NCH)
            asm volatile("cp.async.wait_group 0;\n" ::: "memory");
        else
            asm volatile("cp.async.wait_group 1;\n" ::: "memory");
        __syncwarp();

        const float* sp = slab + (c & 1) * SLOTF + lane * ROWF;
        #pragma unroll
        for (int i = 0; i < 8; ++i) {
            float ft = sp[3 * i];
            float mt = sp[25 + 3 * i];

            float Pc = fmaxf(0.01f, P);
            float Zc = fmaxf(0.01f, Z);
            float gN = N / (chiC + N);
            float zg = rho2 * (1.0f - __expf(-lam005 * Pc)) * Zc;
            float up = gN * ft * Pc;                    // Vm = 1

            float Nn = N + DT * (-up + alp03 * zg + eps01 * P + gam01 * Z
                                 + phi04 * D + mt * (8.0f - N));   // Q0 = 8
            float Pn = P + DT * (up - zg - eps01 * P - eta015 * P - mt * P);
            float Zn = Z + DT * (bet06 * zg - gam01 * Z - mt * Z);
            float Dn = D + DT * (eta015 * P + rem * zg - phi04 * D
                                 - zet01 * D - mt * D);
            N = Nn; P = Pn; Z = Zn; D = Dn;
        }
        o[0][c + 1] = N; o[1][c + 1] = P; o[2][c + 1] = Z; o[3][c + 1] = D;
        __syncwarp();   // slot (c&1) fully consumed before refilling it

        if (c + 2 < NCH)
            issue_chunk(gf, gm, off0, rwrap, c + 2,
                        slab_sh + (uint32_t)(((c & 1) * SLOTF) * 4), lane);
    }

    // ---- per-warp transpose + coalesced stores (warp's ODEs contiguous) ----
    float* trans = slab;                 // 32*33 = 1056 floats, fits in slab
    float* tb = trans + lane * 33;
    #pragma unroll
    for (int cc = 0; cc < 4; ++cc)
        #pragma unroll
        for (int k = 0; k < 8; ++k)
            tb[cc * 8 + k] = o[cc][k];
    __syncwarp();

    float* outb = out + (size_t)t0 * 32;   // 1024 contiguous floats
    #pragma unroll
    for (int it = 0; it < 32; ++it)
        outb[it * 32 + lane] = trans[it * 33 + lane];
}

extern "C" void kernel_launch(void* const* d_in, const int* in_sizes, int n_in,
                              void* d_out, int out_size)
{
    (void)in_sizes; (void)n_in; (void)out_size;
    const float* X_in = (const float*)d_in[0];
    const float* gf   = (const float*)d_in[1];
    const float* gm   = (const float*)d_in[2];
    const float* pvv  = (const float*)d_in[3];
    float* out        = (float*)d_out;

    cudaFuncSetAttribute(npzd_kernel,
                         cudaFuncAttributeMaxDynamicSharedMemorySize,
                         SMEM_BYTES);
    npzd_kernel<<<GRID, NT, SMEM_BYTES>>>(X_in, gf, gm, pvv, out);
}

// round 10
// speedup vs baseline: 1.3311x; 1.3311x over previous
#include <cuda_runtime.h>
#include <cstdint>

// Model_NPZD_68401649156380 — R10: R5's chunked cp.async pipeline with fully
// precomputed addressing (no hot-loop index ALU) and correct final drain.
//
// idx(w,s) = 168w + 3s (exact). Chunk c (8 steps): col = 168w + 24c + 3i.
// Block: 256 threads, G=4 batches, 208 ODE threads. 3-slot smem ring,
// 2 chunks always in flight. Per-thread src/dst offsets precomputed once.

#define NB      2048
#define NWK     52
#define NHRS    8760
#define DT      0.125f
#define NT      256
#define G       4
#define NCOMP   (G * NWK)              // 208
#define NCH     7
#define NSLOT   3
#define IPAD    9                      // float2 per (g,w) per chunk (8 + pad)
#define SLOTF2  (NCOMP * IPAD)         // 1872 float2 per slot
#define SLOTB   (SLOTF2 * 8)           // 14976 bytes
#define SMEM_BYTES (NSLOT * SLOTB)     // 44928
#define CH_ELE  (NCOMP * 8)            // 1664 (f,m) pairs per chunk
#define KMAX    7                      // ceil(1664/256); k=6 only tid<128

__global__ __launch_bounds__(NT, 4) void npzd_kernel(
    const float* __restrict__ X_in,     // (B, 52, 5, 1)
    const float* __restrict__ gf,       // (B, 8760)
    const float* __restrict__ gm,       // (B, 8760)
    const float* __restrict__ pv,       // (B, 10)
    float* __restrict__ out)            // (B, 52, 4, 8)
{
    extern __shared__ float2 ring[];    // [NSLOT][208][IPAD]
    const int tid = threadIdx.x;
    const int b0  = blockIdx.x * G;

    const uint32_t ringsh = (uint32_t)__cvta_generic_to_shared(ring);

    // ---- one-time per-thread load-slot addressing (divisions amortized) ----
    int      srcOff[KMAX];   // gmem float offset (chunk 0); +24 per chunk
    uint32_t dstRel[KMAX];   // smem byte offset within a slot
    #pragma unroll
    for (int k = 0; k < KMAX; ++k) {
        int e = tid + NT * k;
        if (e < CH_ELE) {
            int gw = e >> 3;           // 0..207  (= g*52 + w)
            int i  = e & 7;
            int g  = gw / NWK;
            int w  = gw - g * NWK;
            srcOff[k] = (b0 + g) * NHRS + 168 * w + 3 * i;
            dstRel[k] = (uint32_t)((gw * IPAD + i) * 8);
        } else {
            srcOff[k] = 0; dstRel[k] = 0;
        }
    }

    // ---- issue helper: chunk c into slot (compile-time-ish inline) ----
    auto issue = [&](int c, int slot) {
        const uint32_t sb = ringsh + (uint32_t)(slot * SLOTB);
        const int add = 24 * c;
        #pragma unroll
        for (int k = 0; k < KMAX; ++k) {
            if (k == KMAX - 1 && tid >= (CH_ELE - NT * (KMAX - 1)))
                break;
            const float* fp = gf + (srcOff[k] + add);
            const float* mp = gm + (srcOff[k] + add);
            uint32_t d = sb + dstRel[k];
            asm volatile("cp.async.ca.shared.global [%0], [%1], 4;\n"
                         :: "r"(d), "l"(fp) : "memory");
            asm volatile("cp.async.ca.shared.global [%0], [%1], 4;\n"
                         :: "r"(d + 4), "l"(mp) : "memory");
        }
        asm volatile("cp.async.commit_group;\n" ::: "memory");
    };

    // Prime: chunks 0 and 1 in flight.
    issue(0, 0);
    issue(1, 1);

    // ---- per-thread ODE identity / params (overlaps first gathers) ----
    const int g = tid / NWK;            // valid for tid < NCOMP
    const int w = tid - g * NWK;
    const int b = b0 + g;

    float chiC=0, rho2=0, gam01=0, lam005=0, eps01=0,
          alp03=0, bet06=0, eta015=0, phi04=0, zet01=0, rem=0;
    float N=0, P=0, Z=0, D=0;
    if (tid < NCOMP) {
        const float* p = pv + b * 10;
        chiC   = p[0];
        rho2   = p[1] * 2.0f;
        gam01  = p[2] * 0.1f;
        lam005 = p[3] * 0.05f;
        eps01  = p[4] * 0.1f;
        alp03  = p[5] * 0.3f;
        bet06  = p[6] * 0.6f;
        eta015 = p[7] * 0.15f;
        phi04  = p[8] * 0.4f;
        zet01  = p[9] * 0.1f;
        rem    = 1.0f - alp03 - bet06;

        const float* xi = X_in + ((size_t)(b * NWK + w)) * 5;
        N = xi[1]; P = xi[2]; Z = xi[3]; D = xi[4];
    }

    float o[4][8];
    o[0][0] = N; o[1][0] = P; o[2][0] = Z; o[3][0] = D;

    #pragma unroll 1
    for (int c = 0; c < NCH; ++c) {
        // Ensure chunk c has landed. Final chunk must drain fully.
        if (c == NCH - 1)
            asm volatile("cp.async.wait_group 0;\n" ::: "memory");
        else
            asm volatile("cp.async.wait_group 1;\n" ::: "memory");
        // Cross-warp visibility of slot c%3 AND slot (c+2)%3 fully consumed.
        __syncthreads();

        if (c + 2 < NCH)
            issue(c + 2, (c + 2) % NSLOT);

        if (tid < NCOMP) {
            const float2* sp = ring + (c % NSLOT) * SLOTF2 + tid * IPAD;
            #pragma unroll
            for (int i = 0; i < 8; ++i) {
                float2 fm = sp[i];
                float ft = fm.x, mt = fm.y;

                float Pc = fmaxf(0.01f, P);
                float Zc = fmaxf(0.01f, Z);
                float gN = N / (chiC + N);
                float zg = rho2 * (1.0f - __expf(-lam005 * Pc)) * Zc;
                float up = gN * ft * Pc;                    // Vm = 1

                float Nn = N + DT * (-up + alp03 * zg + eps01 * P + gam01 * Z
                                     + phi04 * D + mt * (8.0f - N));   // Q0=8
                float Pn = P + DT * (up - zg - eps01 * P - eta015 * P - mt * P);
                float Zn = Z + DT * (bet06 * zg - gam01 * Z - mt * Z);
                float Dn = D + DT * (eta015 * P + rem * zg - phi04 * D
                                     - zet01 * D - mt * D);
                N = Nn; P = Pn; Z = Zn; D = Dn;
            }
            o[0][c + 1] = N; o[1][c + 1] = P; o[2][c + 1] = Z; o[3][c + 1] = D;
        }
    }
    __syncthreads();   // all ring reads done; reuse smem for output transpose

    // ---- transpose through smem, coalesced output stores ----
    float* obuf = (float*)ring;          // 208*33 = 6864 floats, fits
    if (tid < NCOMP) {
        float* ob = obuf + tid * 33;
        #pragma unroll
        for (int cc = 0; cc < 4; ++cc)
            #pragma unroll
            for (int k = 0; k < 8; ++k)
                ob[cc * 8 + k] = o[cc][k];
    }
    __syncthreads();

    float* outb = out + (size_t)blockIdx.x * (NCOMP * 32);
    #pragma unroll
    for (int i = tid; i < NCOMP * 32; i += NT) {
        int t2 = i >> 5;
        int m  = i & 31;
        outb[i] = obuf[t2 * 33 + m];
    }
}

extern "C" void kernel_launch(void* const* d_in, const int* in_sizes, int n_in,
                              void* d_out, int out_size)
{
    (void)in_sizes; (void)n_in; (void)out_size;
    const float* X_in = (const float*)d_in[0];
    const float* gf   = (const float*)d_in[1];
    const float* gm   = (const float*)d_in[2];
    const float* pvv  = (const float*)d_in[3];
    float* out        = (float*)d_out;

    cudaFuncSetAttribute(npzd_kernel,
                         cudaFuncAttributeMaxDynamicSharedMemorySize,
                         SMEM_BYTES);
    npzd_kernel<<<NB / G, NT, SMEM_BYTES>>>(X_in, gf, gm, pvv, out);
}

// round 12
// speedup vs baseline: 1.3347x; 1.0027x over previous
#include <cuda_runtime.h>
#include <cstdint>

// Model_NPZD_68401649156380 — R12: R11 (16B cp.async chunk pipeline) with the
// smem-destination alignment bug fixed: row stride 52 floats = 208 B (16B
// multiple). Trade: 4-way LDS bank conflict in the compute phase (cheap).
//
// Per chunk c (8 steps), each ODE row needs floats [24c, 24c+24) of its
// contiguous 168-float forcing row (used cols are 24c+3i). Load the 96B span
// as 6 x float4 cp.async per row per array (all bytes needed, perfect
// sectors). Block: 256 threads, G=2 batches (104 ODEs), 3-slot ring,
// 2 chunks in flight, 64.9KB smem -> 3 blocks/SM.

#define NB      2048
#define NWK     52
#define NHRS    8760
#define DT      0.125f
#define NT      256
#define G       2
#define NCOMP   (G * NWK)              // 104
#define NCH     7
#define NSLOT   3
#define RSTR    52                     // floats per row: 24 f | 24 m | 4 pad (208B)
#define SLOTF   (NCOMP * RSTR)         // 5408 floats
#define SLOTB   (SLOTF * 4)            // 21632 bytes (16B multiple)
#define SMEM_BYTES (NSLOT * SLOTB)     // 64896
#define NE      (NCOMP * 6)            // 624 float4-span units per chunk
#define KMAX    3                      // ceil(624/256); k=2 only tid<112

__global__ __launch_bounds__(NT) void npzd_kernel(
    const float* __restrict__ X_in,     // (B, 52, 5, 1)
    const float* __restrict__ gf,       // (B, 8760)
    const float* __restrict__ gm,       // (B, 8760)
    const float* __restrict__ pv,       // (B, 10)
    float* __restrict__ out)            // (B, 52, 4, 8)
{
    extern __shared__ float ring[];     // [NSLOT][104][52]
    const int tid = threadIdx.x;
    const int b0  = blockIdx.x * G;

    const uint32_t ringsh = (uint32_t)__cvta_generic_to_shared(ring);

    // ---- one-time per-thread addressing: e = tid + 256k, e < 624 ----
    // e -> (gw, q): gw = e/6 (row 0..103), q = e%6 (float4 within 96B span)
    int      srcOff[KMAX];   // gmem float offset for chunk 0; +24 per chunk
    uint32_t dstF[KMAX];     // smem byte offset of f float4 within a slot
    #pragma unroll
    for (int k = 0; k < KMAX; ++k) {
        int e = tid + NT * k;
        if (e < NE) {
            int gw = e / 6;
            int q  = e - 6 * gw;
            int g  = gw / NWK;
            int w  = gw - g * NWK;
            srcOff[k] = (b0 + g) * NHRS + 168 * w + 4 * q;
            dstF[k]   = (uint32_t)((gw * RSTR + 4 * q) * 4);   // 16B aligned
        } else { srcOff[k] = 0; dstF[k] = 0; }
    }

    auto issue = [&](int c, int slot) {
        const uint32_t sb  = ringsh + (uint32_t)(slot * SLOTB);
        const int      add = 24 * c;
        #pragma unroll
        for (int k = 0; k < KMAX; ++k) {
            if (k == KMAX - 1 && tid >= (NE - NT * (KMAX - 1)))
                break;
            const float* fp = gf + (srcOff[k] + add);
            const float* mp = gm + (srcOff[k] + add);
            uint32_t d = sb + dstF[k];
            asm volatile("cp.async.ca.shared.global [%0], [%1], 16;\n"
                         :: "r"(d), "l"(fp) : "memory");
            asm volatile("cp.async.ca.shared.global [%0], [%1], 16;\n"
                         :: "r"(d + 96), "l"(mp) : "memory");  // m at +24 floats
        }
        asm volatile("cp.async.commit_group;\n" ::: "memory");
    };

    // Prime: chunks 0 and 1 in flight.
    issue(0, 0);
    issue(1, 1);

    // ---- per-thread ODE identity / params (overlaps first gathers) ----
    const int g = tid / NWK;            // valid for tid < NCOMP
    const int w = tid - g * NWK;
    const int b = b0 + g;

    float chiC=0, rho2=0, gam01=0, lam005=0, eps01=0,
          alp03=0, bet06=0, eta015=0, phi04=0, zet01=0, rem=0;
    float N=0, P=0, Z=0, D=0;
    if (tid < NCOMP) {
        const float* p = pv + b * 10;
        chiC   = p[0];
        rho2   = p[1] * 2.0f;
        gam01  = p[2] * 0.1f;
        lam005 = p[3] * 0.05f;
        eps01  = p[4] * 0.1f;
        alp03  = p[5] * 0.3f;
        bet06  = p[6] * 0.6f;
        eta015 = p[7] * 0.15f;
        phi04  = p[8] * 0.4f;
        zet01  = p[9] * 0.1f;
        rem    = 1.0f - alp03 - bet06;

        const float* xi = X_in + ((size_t)(b * NWK + w)) * 5;
        N = xi[1]; P = xi[2]; Z = xi[3]; D = xi[4];
    }

    float o[4][8];
    o[0][0] = N; o[1][0] = P; o[2][0] = Z; o[3][0] = D;

    #pragma unroll 1
    for (int c = 0; c < NCH; ++c) {
        if (c == NCH - 1)
            asm volatile("cp.async.wait_group 0;\n" ::: "memory");
        else
            asm volatile("cp.async.wait_group 1;\n" ::: "memory");
        __syncthreads();   // chunk c visible; slot (c-1)%3 fully consumed

        if (c + 2 < NCH)
            issue(c + 2, (c + 2) % NSLOT);

        if (tid < NCOMP) {
            const float* sp = ring + (c % NSLOT) * SLOTF + tid * RSTR;
            #pragma unroll
            for (int i = 0; i < 8; ++i) {
                float ft = sp[3 * i];
                float mt = sp[24 + 3 * i];

                float Pc = fmaxf(0.01f, P);
                float Zc = fmaxf(0.01f, Z);
                float gN = N / (chiC + N);
                float zg = rho2 * (1.0f - __expf(-lam005 * Pc)) * Zc;
                float up = gN * ft * Pc;                    // Vm = 1

                float Nn = N + DT * (-up + alp03 * zg + eps01 * P + gam01 * Z
                                     + phi04 * D + mt * (8.0f - N));   // Q0=8
                float Pn = P + DT * (up - zg - eps01 * P - eta015 * P - mt * P);
                float Zn = Z + DT * (bet06 * zg - gam01 * Z - mt * Z);
                float Dn = D + DT * (eta015 * P + rem * zg - phi04 * D
                                     - zet01 * D - mt * D);
                N = Nn; P = Pn; Z = Zn; D = Dn;
            }
            o[0][c + 1] = N; o[1][c + 1] = P; o[2][c + 1] = Z; o[3][c + 1] = D;
        }
    }
    __syncthreads();   // all ring reads done; reuse smem

    // ---- transpose through smem, coalesced output stores ----
    float* obuf = ring;                  // 104*33 = 3432 floats, fits
    if (tid < NCOMP) {
        float* ob = obuf + tid * 33;
        #pragma unroll
        for (int cc = 0; cc < 4; ++cc)
            #pragma unroll
            for (int k = 0; k < 8; ++k)
                ob[cc * 8 + k] = o[cc][k];
    }
    __syncthreads();

    float* outb = out + (size_t)blockIdx.x * (NCOMP * 32);
    #pragma unroll
    for (int i = tid; i < NCOMP * 32; i += NT) {
        int t2 = i >> 5;
        int m  = i & 31;
        outb[i] = obuf[t2 * 33 + m];
    }
}

extern "C" void kernel_launch(void* const* d_in, const int* in_sizes, int n_in,
                              void* d_out, int out_size)
{
    (void)in_sizes; (void)n_in; (void)out_size;
    const float* X_in = (const float*)d_in[0];
    const float* gf   = (const float*)d_in[1];
    const float* gm   = (const float*)d_in[2];
    const float* pvv  = (const float*)d_in[3];
    float* out        = (float*)d_out;

    cudaFuncSetAttribute(npzd_kernel,
                         cudaFuncAttributeMaxDynamicSharedMemorySize,
                         SMEM_BYTES);
    npzd_kernel<<<NB / G, NT, SMEM_BYTES>>>(X_in, gf, gm, pvv, out);
}